// round 2
// baseline (speedup 1.0000x reference)
#include <cuda_runtime.h>

#define T_STEPS 32
#define B_SZ    512
#define S_SZ    64
#define F_INDIM 128
#define H1      256
#define H2      256
#define H3      128

// Scratch (no cudaMalloc allowed): device globals.
__device__ float g_spk0[T_STEPS * B_SZ * F_INDIM];   // 8 MB
__device__ float g_spk1[T_STEPS * B_SZ * H1];        // 16 MB
__device__ float g_spk2[T_STEPS * B_SZ * H2];        // 16 MB
__device__ float g_Wt1[F_INDIM * H1];
__device__ float g_Wt2[H1 * H2];
__device__ float g_Wt3[H2 * H3];

// ---- packed f32x2 helpers (sm_103a FFMA2 path, PTX-only) -------------------
__device__ __forceinline__ unsigned long long fma2(unsigned long long a,
                                                   unsigned long long b,
                                                   unsigned long long c) {
    unsigned long long d;
    asm("fma.rn.f32x2 %0, %1, %2, %3;" : "=l"(d) : "l"(a), "l"(b), "l"(c));
    return d;
}
__device__ __forceinline__ unsigned long long bcast2(float v) {
    unsigned long long d;
    asm("mov.b64 %0, {%1, %2};" : "=l"(d) : "f"(v), "f"(v));
    return d;
}
__device__ __forceinline__ float2 unpack2(unsigned long long p) {
    float2 r;
    asm("mov.b64 {%0, %1}, %2;" : "=f"(r.x), "=f"(r.y) : "l"(p));
    return r;
}

// ---------------------------------------------------------------------------
// Transpose W[h,i] (H x IN, row-major) -> Wt[i,h].
// ---------------------------------------------------------------------------
__global__ void transpose_kernel(const float* __restrict__ W,
                                 float* __restrict__ Wt, int H, int IN) {
    int idx = blockIdx.x * blockDim.x + threadIdx.x;
    if (idx < H * IN) {
        int i = idx / H;
        int h = idx - i * H;
        Wt[idx] = W[h * IN + i];
    }
}

// ---------------------------------------------------------------------------
// Latency encoder. One CTA per batch element: stage x[b,:,:] (32KB) in smem,
// then one thread per f runs both passes against smem (no strided global
// re-reads). Math identical to snntorch spikegen.latency(normalize=True).
// ---------------------------------------------------------------------------
__global__ void __launch_bounds__(F_INDIM)
encode_kernel(const float* __restrict__ x, float* __restrict__ out) {
    __shared__ float sx[S_SZ * F_INDIM];   // 32 KB

    const int b = blockIdx.x;
    const int f = threadIdx.x;

    const float* xb = x + (size_t)b * (S_SZ * F_INDIM);
#pragma unroll 4
    for (int idx = f; idx < S_SZ * F_INDIM; idx += F_INDIM)
        sx[idx] = xb[idx];
    __syncthreads();

    // pass 1: min/max of gated values over the sequence dim
    float mn = 1e30f, mx = -1e30f;
#pragma unroll 8
    for (int s = 0; s < S_SZ; ++s) {
        float v = sx[s * F_INDIM + f];
        float g = (v < 0.75f) ? 0.0f : v;
        mn = fminf(mn, g);
        mx = fmaxf(mx, g);
    }
    float denom = mx - mn + 1e-8f;

    // np.float32(np.log((0.01 + 1e-7) / 1e-7))
    const float TMAX = 11.512935464920229f;

    unsigned char cnt[T_STEPS];
#pragma unroll
    for (int t = 0; t < T_STEPS; ++t) cnt[t] = 0;

    // pass 2: latency code + histogram
#pragma unroll 4
    for (int s = 0; s < S_SZ; ++s) {
        float v = sx[s * F_INDIM + f];
        float g = (v < 0.75f) ? 0.0f : v;
        float xn = (g - mn) / denom;
        float d  = fmaxf(xn, 0.0100001f);          // clip(xn, LAT_THR+EPS)
        float lg = logf(d / (d - 0.01f));
        float tt = (lg * 31.0f) / TMAX;
        float tr = rintf(tt);                      // round half-to-even
        tr = fminf(fmaxf(tr, 0.0f), 31.0f);
        cnt[(int)tr]++;
    }

#pragma unroll
    for (int t = 0; t < T_STEPS; ++t) {
        out[((size_t)t * B_SZ + b) * F_INDIM + f] = (float)cnt[t] * (1.0f / 64.0f);
    }
}

// ---------------------------------------------------------------------------
// Fused Linear + LIF layer with packed f32x2 FMAs.
// One CTA per batch element b, one thread per output neuron h.
// Input tile restaged i-major (pad 36) so timesteps (t, t+1) are contiguous:
// one LDS.128 broadcast yields two f32x2 operands covering t..t+3.
// ---------------------------------------------------------------------------
template <int IN, int H>
__global__ void __launch_bounds__(H)
layer_kernel(const float* __restrict__ in, const float* __restrict__ Wt,
             const float* __restrict__ bias, float* __restrict__ out) {
    constexpr int PAD = 36;                 // 144B row: 16B-aligned, few conflicts
    __shared__ float s_in[IN * PAD];

    const int b = blockIdx.x;
    const int h = threadIdx.x;

    // Stage: read global coalesced (t-major), write i-major.
    for (int idx = h; idx < T_STEPS * IN; idx += H) {
        int t = idx / IN;
        int i = idx - t * IN;
        s_in[i * PAD + t] = in[((size_t)t * B_SZ + b) * IN + i];
    }
    __syncthreads();

    unsigned long long acc2[T_STEPS / 2];
#pragma unroll
    for (int p = 0; p < T_STEPS / 2; ++p) acc2[p] = 0ULL;

    // i-blocked by 4: 4 LDG (L1-resident weights) + 32 LDS.128 + 64 FFMA2.
    for (int i = 0; i < IN; i += 4) {
        unsigned long long wp0 = bcast2(Wt[(i + 0) * H + h]);
        unsigned long long wp1 = bcast2(Wt[(i + 1) * H + h]);
        unsigned long long wp2 = bcast2(Wt[(i + 2) * H + h]);
        unsigned long long wp3 = bcast2(Wt[(i + 3) * H + h]);
#pragma unroll
        for (int j = 0; j < 8; ++j) {       // 8 float4 = 32 timesteps
            ulonglong2 s0 = *reinterpret_cast<const ulonglong2*>(&s_in[(i + 0) * PAD + 4 * j]);
            ulonglong2 s1 = *reinterpret_cast<const ulonglong2*>(&s_in[(i + 1) * PAD + 4 * j]);
            ulonglong2 s2 = *reinterpret_cast<const ulonglong2*>(&s_in[(i + 2) * PAD + 4 * j]);
            ulonglong2 s3 = *reinterpret_cast<const ulonglong2*>(&s_in[(i + 3) * PAD + 4 * j]);
            acc2[2 * j + 0] = fma2(wp0, s0.x, acc2[2 * j + 0]);
            acc2[2 * j + 1] = fma2(wp0, s0.y, acc2[2 * j + 1]);
            acc2[2 * j + 0] = fma2(wp1, s1.x, acc2[2 * j + 0]);
            acc2[2 * j + 1] = fma2(wp1, s1.y, acc2[2 * j + 1]);
            acc2[2 * j + 0] = fma2(wp2, s2.x, acc2[2 * j + 0]);
            acc2[2 * j + 1] = fma2(wp2, s2.y, acc2[2 * j + 1]);
            acc2[2 * j + 0] = fma2(wp3, s3.x, acc2[2 * j + 0]);
            acc2[2 * j + 1] = fma2(wp3, s3.y, acc2[2 * j + 1]);
        }
    }

    // LIF scan (reset-by-subtraction), fp32 ops in reference order.
    const float bv = bias[h];
    float mem = 0.0f;
#pragma unroll
    for (int p = 0; p < T_STEPS / 2; ++p) {
        float2 a = unpack2(acc2[p]);
        {
            float cur = __fadd_rn(a.x, bv);
            float r   = (mem > 1.0f) ? 1.0f : 0.0f;
            mem = __fsub_rn(__fadd_rn(__fmul_rn(0.9f, mem), cur), r);
            out[((size_t)(2 * p) * B_SZ + b) * H + h] = (mem > 1.0f) ? 1.0f : 0.0f;
        }
        {
            float cur = __fadd_rn(a.y, bv);
            float r   = (mem > 1.0f) ? 1.0f : 0.0f;
            mem = __fsub_rn(__fadd_rn(__fmul_rn(0.9f, mem), cur), r);
            out[((size_t)(2 * p + 1) * B_SZ + b) * H + h] = (mem > 1.0f) ? 1.0f : 0.0f;
        }
    }
}

// ---------------------------------------------------------------------------
extern "C" void kernel_launch(void* const* d_in, const int* in_sizes, int n_in,
                              void* d_out, int out_size) {
    const float* x  = (const float*)d_in[0];
    const float* W1 = (const float*)d_in[1];
    const float* b1 = (const float*)d_in[2];
    const float* W2 = (const float*)d_in[3];
    const float* b2 = (const float*)d_in[4];
    const float* W3 = (const float*)d_in[5];
    const float* b3 = (const float*)d_in[6];
    float* out = (float*)d_out;

    float *spk0, *spk1, *spk2, *wt1, *wt2, *wt3;
    cudaGetSymbolAddress((void**)&spk0, g_spk0);
    cudaGetSymbolAddress((void**)&spk1, g_spk1);
    cudaGetSymbolAddress((void**)&spk2, g_spk2);
    cudaGetSymbolAddress((void**)&wt1, g_Wt1);
    cudaGetSymbolAddress((void**)&wt2, g_Wt2);
    cudaGetSymbolAddress((void**)&wt3, g_Wt3);

    transpose_kernel<<<(H1 * F_INDIM + 255) / 256, 256>>>(W1, wt1, H1, F_INDIM);
    transpose_kernel<<<(H2 * H1 + 255) / 256, 256>>>(W2, wt2, H2, H1);
    transpose_kernel<<<(H3 * H2 + 255) / 256, 256>>>(W3, wt3, H3, H2);

    encode_kernel<<<B_SZ, F_INDIM>>>(x, spk0);

    layer_kernel<F_INDIM, H1><<<B_SZ, H1>>>(spk0, wt1, b1, spk1);
    layer_kernel<H1, H2><<<B_SZ, H2>>>(spk1, wt2, b2, spk2);
    layer_kernel<H2, H3><<<B_SZ, H3>>>(spk2, wt3, b3, out);
}

// round 3
// speedup vs baseline: 1.4863x; 1.4863x over previous
#include <cuda_runtime.h>

#define T_STEPS 32
#define B_SZ    512
#define S_SZ    64
#define F_INDIM 128
#define H1      256
#define H2      256
#define H3      128
#define M_ROWS  (T_STEPS * B_SZ)   // 16384

// Scratch (no cudaMalloc allowed): device globals. Spike buffers are b-major:
// row r = b*32 + t, so a 64-row GEMM tile holds full time series for 2 b's.
__device__ float g_spk0[M_ROWS * F_INDIM];   // 8 MB
__device__ float g_spk1[M_ROWS * H1];        // 16 MB
__device__ float g_spk2[M_ROWS * H2];        // 16 MB
__device__ float g_Wt1[F_INDIM * H1];
__device__ float g_Wt2[H1 * H2];
__device__ float g_Wt3[H2 * H3];

// ---- packed f32x2 helpers (sm_103a FFMA2, PTX-only) ------------------------
__device__ __forceinline__ unsigned long long fma2(unsigned long long a,
                                                   unsigned long long b,
                                                   unsigned long long c) {
    unsigned long long d;
    asm("fma.rn.f32x2 %0, %1, %2, %3;" : "=l"(d) : "l"(a), "l"(b), "l"(c));
    return d;
}
__device__ __forceinline__ unsigned long long bcast2(float v) {
    unsigned long long d;
    asm("mov.b64 %0, {%1, %2};" : "=l"(d) : "f"(v), "f"(v));
    return d;
}

// ---------------------------------------------------------------------------
// Transpose W[h,i] (H x IN) -> Wt[i,h].
// ---------------------------------------------------------------------------
__global__ void transpose_kernel(const float* __restrict__ W,
                                 float* __restrict__ Wt, int H, int IN) {
    int idx = blockIdx.x * blockDim.x + threadIdx.x;
    if (idx < H * IN) {
        int i = idx / H;
        int h = idx - i * H;
        Wt[idx] = W[h * IN + i];
    }
}

// ---------------------------------------------------------------------------
// Latency encoder, 4-way s-split per (b,f). One CTA per b, 512 threads:
// thread (f, j) handles s = j*16 .. j*16+15 (kept in registers), min/max and
// packed 8-bit histograms merged across the 4 j-lanes with shfl.bfly.
// All merges are exact (fmin/fmax + integer counts). Output b-major.
// ---------------------------------------------------------------------------
__global__ void __launch_bounds__(512)
encode_kernel(const float* __restrict__ x, float* __restrict__ out) {
    const int b = blockIdx.x;
    const int f = threadIdx.x >> 2;
    const int j = threadIdx.x & 3;

    const float* xp = x + (size_t)b * (S_SZ * F_INDIM) + f;

    float v[16];
#pragma unroll
    for (int s = 0; s < 16; ++s) {
        float raw = xp[(j * 16 + s) * F_INDIM];
        v[s] = (raw < 0.75f) ? 0.0f : raw;     // ENC_THR gate
    }

    float mn = v[0], mx = v[0];
#pragma unroll
    for (int s = 1; s < 16; ++s) {
        mn = fminf(mn, v[s]);
        mx = fmaxf(mx, v[s]);
    }
    mn = fminf(mn, __shfl_xor_sync(0xFFFFFFFFu, mn, 1));
    mn = fminf(mn, __shfl_xor_sync(0xFFFFFFFFu, mn, 2));
    mx = fmaxf(mx, __shfl_xor_sync(0xFFFFFFFFu, mx, 1));
    mx = fmaxf(mx, __shfl_xor_sync(0xFFFFFFFFu, mx, 2));

    float denom = mx - mn + 1e-8f;
    const float TMAX = 11.512935464920229f;   // np.float32(log((0.01+1e-7)/1e-7))

    unsigned pk[8];
#pragma unroll
    for (int i = 0; i < 8; ++i) pk[i] = 0u;

#pragma unroll
    for (int s = 0; s < 16; ++s) {
        float xn = (v[s] - mn) / denom;
        float d  = fmaxf(xn, 0.0100001f);      // clip(xn, LAT_THR+EPS)
        float lg = logf(d / (d - 0.01f));
        float tt = (lg * 31.0f) / TMAX;
        float tr = rintf(tt);                  // round half-to-even
        tr = fminf(fmaxf(tr, 0.0f), 31.0f);
        int t = (int)tr;
        pk[t >> 2] += 1u << ((t & 3) * 8);
    }
#pragma unroll
    for (int i = 0; i < 8; ++i) {
        pk[i] += __shfl_xor_sync(0xFFFFFFFFu, pk[i], 1);
        pk[i] += __shfl_xor_sync(0xFFFFFFFFu, pk[i], 2);
    }

    // lane j writes t = j*8 .. j*8+7
#pragma unroll
    for (int i = 0; i < 8; ++i) {
        int t = j * 8 + i;
        unsigned c = (pk[t >> 2] >> ((t & 3) * 8)) & 0xFFu;
        out[((size_t)b * T_STEPS + t) * F_INDIM + f] = (float)c * (1.0f / 64.0f);
    }
}

// ---------------------------------------------------------------------------
// Fused SGEMM (64x128 tile, K-chunk 32, FFMA2) + LIF scan epilogue.
// Each output keeps a single ascending-k FMA chain -> bitwise-exact vs ref.
// TMAJ: write spikes t-major (final layer -> d_out), else b-major.
// ---------------------------------------------------------------------------
template <int IN, int H, bool TMAJ>
__global__ void __launch_bounds__(256, 2)
layer_kernel(const float* __restrict__ in, const float* __restrict__ Wt,
             const float* __restrict__ bias, float* __restrict__ out) {
    __shared__ float sm[8320];                // max(stage 6400, scur 64*130)
    float* sA = sm;                           // [32][72]  (A^T: k-major, pad 8)
    float* sB = sm + 32 * 72;                 // [32][128]

    const int tid = threadIdx.x;
    const int r0  = blockIdx.x * 64;
    const int N0  = blockIdx.y * 128;
    const int tm  = tid & 15;
    const int tn  = tid >> 4;
    const int m0  = tm * 4;
    const int n0  = tn * 8;

    // staging coords
    const int am0 = tid >> 3;                 // A: v=tid      -> m, kc
    const int am1 = (tid + 256) >> 3;         //    v=tid+256  (same kc)
    const int akc = tid & 7;
    const int bk0 = tid >> 5;                 // B: k_i = bk0 + i*8
    const int bnc = tid & 31;

    const float* Ag = in + (size_t)r0 * IN;
    const float* Bg = Wt + N0;

    constexpr int NCH = IN / 32;

    float4 pa0, pa1, pb[4];
    // prefetch chunk 0
    pa0 = *(const float4*)&Ag[(size_t)am0 * IN + akc * 4];
    pa1 = *(const float4*)&Ag[(size_t)am1 * IN + akc * 4];
#pragma unroll
    for (int i = 0; i < 4; ++i)
        pb[i] = *(const float4*)&Bg[(size_t)(bk0 + i * 8) * H + bnc * 4];

    unsigned long long acc[4][4];
#pragma unroll
    for (int mi = 0; mi < 4; ++mi)
#pragma unroll
        for (int nj = 0; nj < 4; ++nj) acc[mi][nj] = 0ULL;

#pragma unroll 1
    for (int c = 0; c < NCH; ++c) {
        // store staged regs (A transposed to k-major)
        sA[(akc * 4 + 0) * 72 + am0] = pa0.x;
        sA[(akc * 4 + 1) * 72 + am0] = pa0.y;
        sA[(akc * 4 + 2) * 72 + am0] = pa0.z;
        sA[(akc * 4 + 3) * 72 + am0] = pa0.w;
        sA[(akc * 4 + 0) * 72 + am1] = pa1.x;
        sA[(akc * 4 + 1) * 72 + am1] = pa1.y;
        sA[(akc * 4 + 2) * 72 + am1] = pa1.z;
        sA[(akc * 4 + 3) * 72 + am1] = pa1.w;
#pragma unroll
        for (int i = 0; i < 4; ++i)
            *(float4*)&sB[(bk0 + i * 8) * 128 + bnc * 4] = pb[i];
        __syncthreads();

        if (c + 1 < NCH) {
            const int k0 = (c + 1) * 32;
            pa0 = *(const float4*)&Ag[(size_t)am0 * IN + k0 + akc * 4];
            pa1 = *(const float4*)&Ag[(size_t)am1 * IN + k0 + akc * 4];
#pragma unroll
            for (int i = 0; i < 4; ++i)
                pb[i] = *(const float4*)&Bg[(size_t)(k0 + bk0 + i * 8) * H + bnc * 4];
        }

#pragma unroll
        for (int k = 0; k < 32; ++k) {
            float4 av = *(const float4*)&sA[k * 72 + m0];
            ulonglong2 b01 = *(const ulonglong2*)&sB[k * 128 + n0];
            ulonglong2 b23 = *(const ulonglong2*)&sB[k * 128 + n0 + 4];
            unsigned long long a0 = bcast2(av.x);
            unsigned long long a1 = bcast2(av.y);
            unsigned long long a2 = bcast2(av.z);
            unsigned long long a3 = bcast2(av.w);
            acc[0][0] = fma2(a0, b01.x, acc[0][0]);
            acc[0][1] = fma2(a0, b01.y, acc[0][1]);
            acc[0][2] = fma2(a0, b23.x, acc[0][2]);
            acc[0][3] = fma2(a0, b23.y, acc[0][3]);
            acc[1][0] = fma2(a1, b01.x, acc[1][0]);
            acc[1][1] = fma2(a1, b01.y, acc[1][1]);
            acc[1][2] = fma2(a1, b23.x, acc[1][2]);
            acc[1][3] = fma2(a1, b23.y, acc[1][3]);
            acc[2][0] = fma2(a2, b01.x, acc[2][0]);
            acc[2][1] = fma2(a2, b01.y, acc[2][1]);
            acc[2][2] = fma2(a2, b23.x, acc[2][2]);
            acc[2][3] = fma2(a2, b23.y, acc[2][3]);
            acc[3][0] = fma2(a3, b01.x, acc[3][0]);
            acc[3][1] = fma2(a3, b01.y, acc[3][1]);
            acc[3][2] = fma2(a3, b23.x, acc[3][2]);
            acc[3][3] = fma2(a3, b23.y, acc[3][3]);
        }
        __syncthreads();
    }

    // Epilogue: stage cur tile in smem [m][h] (stride 130 keeps 8B alignment
    // and conflict-free column reads), then fused LIF scan.
    float* scur = sm;
#pragma unroll
    for (int mi = 0; mi < 4; ++mi)
#pragma unroll
        for (int nj = 0; nj < 4; ++nj)
            *(unsigned long long*)&scur[(size_t)(m0 + mi) * 130 + n0 + nj * 2] = acc[mi][nj];
    __syncthreads();

    const int bl = tid >> 7;                  // 0..1 (b within tile)
    const int h  = tid & 127;
    const float bv = bias[N0 + h];
    const int bglob = blockIdx.x * 2 + bl;

    float mem = 0.0f;
#pragma unroll
    for (int t = 0; t < T_STEPS; ++t) {
        float a   = scur[(bl * 32 + t) * 130 + h];
        float cur = __fadd_rn(a, bv);
        float r   = (mem > 1.0f) ? 1.0f : 0.0f;
        mem = __fsub_rn(__fadd_rn(__fmul_rn(0.9f, mem), cur), r);
        float spk = (mem > 1.0f) ? 1.0f : 0.0f;
        size_t o = TMAJ ? ((size_t)(t * B_SZ + bglob) * H + N0 + h)
                        : ((size_t)(r0 + bl * 32 + t) * H + N0 + h);
        out[o] = spk;
    }
}

// ---------------------------------------------------------------------------
extern "C" void kernel_launch(void* const* d_in, const int* in_sizes, int n_in,
                              void* d_out, int out_size) {
    const float* x  = (const float*)d_in[0];
    const float* W1 = (const float*)d_in[1];
    const float* b1 = (const float*)d_in[2];
    const float* W2 = (const float*)d_in[3];
    const float* b2 = (const float*)d_in[4];
    const float* W3 = (const float*)d_in[5];
    const float* b3 = (const float*)d_in[6];
    float* out = (float*)d_out;

    float *spk0, *spk1, *spk2, *wt1, *wt2, *wt3;
    cudaGetSymbolAddress((void**)&spk0, g_spk0);
    cudaGetSymbolAddress((void**)&spk1, g_spk1);
    cudaGetSymbolAddress((void**)&spk2, g_spk2);
    cudaGetSymbolAddress((void**)&wt1, g_Wt1);
    cudaGetSymbolAddress((void**)&wt2, g_Wt2);
    cudaGetSymbolAddress((void**)&wt3, g_Wt3);

    transpose_kernel<<<(H1 * F_INDIM + 255) / 256, 256>>>(W1, wt1, H1, F_INDIM);
    transpose_kernel<<<(H2 * H1 + 255) / 256, 256>>>(W2, wt2, H2, H1);
    transpose_kernel<<<(H3 * H2 + 255) / 256, 256>>>(W3, wt3, H3, H2);

    encode_kernel<<<B_SZ, 512>>>(x, spk0);

    layer_kernel<F_INDIM, H1, false><<<dim3(M_ROWS / 64, H1 / 128), 256>>>(spk0, wt1, b1, spk1);
    layer_kernel<H1, H2, false><<<dim3(M_ROWS / 64, H2 / 128), 256>>>(spk1, wt2, b2, spk2);
    layer_kernel<H2, H3, true><<<dim3(M_ROWS / 64, H3 / 128), 256>>>(spk2, wt3, b3, out);
}

// round 5
// speedup vs baseline: 2.7517x; 1.8514x over previous
#include <cuda_runtime.h>
#include <cuda_bf16.h>
#include <cstdint>

#define T_STEPS 32
#define B_SZ    512
#define S_SZ    64
#define F_INDIM 128
#define H1      256
#define H2      256
#define H3      128
#define M_ROWS  (T_STEPS * B_SZ)   // 16384

// Scratch (no cudaMalloc): device globals. Spike buffers b-major: row = b*32+t.
__device__ __nv_bfloat16 g_spk0[M_ROWS * F_INDIM];
__device__ __nv_bfloat16 g_spk1[M_ROWS * H1];
__device__ __nv_bfloat16 g_spk2[M_ROWS * H2];
__device__ __nv_bfloat16 g_W1s[3 * H1 * F_INDIM];   // [split][h][i] (k-contiguous)
__device__ __nv_bfloat16 g_W2s[3 * H2 * H1];
__device__ __nv_bfloat16 g_W3s[3 * H3 * H2];

__device__ __forceinline__ uint32_t smem_u32(const void* p) {
    uint32_t a;
    asm("{ .reg .u64 t; cvta.to.shared.u64 t, %1; cvt.u32.u64 %0, t; }" : "=r"(a) : "l"(p));
    return a;
}
__device__ __forceinline__ void ldsm4(uint32_t& r0, uint32_t& r1, uint32_t& r2,
                                      uint32_t& r3, uint32_t addr) {
    asm volatile("ldmatrix.sync.aligned.m8n8.x4.shared.b16 {%0,%1,%2,%3}, [%4];"
                 : "=r"(r0), "=r"(r1), "=r"(r2), "=r"(r3) : "r"(addr));
}
__device__ __forceinline__ void mma16816(float* c, const uint32_t* a,
                                         uint32_t b0, uint32_t b1) {
    asm volatile(
        "mma.sync.aligned.m16n8k16.row.col.f32.bf16.bf16.f32 "
        "{%0,%1,%2,%3}, {%4,%5,%6,%7}, {%8,%9}, {%0,%1,%2,%3};"
        : "+f"(c[0]), "+f"(c[1]), "+f"(c[2]), "+f"(c[3])
        : "r"(a[0]), "r"(a[1]), "r"(a[2]), "r"(a[3]), "r"(b0), "r"(b1));
}

// ---------------------------------------------------------------------------
// Weight split: W -> (bf16 hi, mid, lo); split steps are exact in fp32.
// ---------------------------------------------------------------------------
__global__ void split_kernel(const float* __restrict__ W,
                             __nv_bfloat16* __restrict__ Ws, int n) {
    int idx = blockIdx.x * blockDim.x + threadIdx.x;
    if (idx >= n) return;
    float w = W[idx];
    __nv_bfloat16 h1 = __float2bfloat16_rn(w);
    float r1 = w - __bfloat162float(h1);
    __nv_bfloat16 h2 = __float2bfloat16_rn(r1);
    float r2 = r1 - __bfloat162float(h2);
    __nv_bfloat16 h3 = __float2bfloat16_rn(r2);
    Ws[idx]         = h1;
    Ws[n + idx]     = h2;
    Ws[2 * n + idx] = h3;
}

// ---------------------------------------------------------------------------
// Latency encoder (proven R3 math), output bf16 b-major (exact: counts/64).
// ---------------------------------------------------------------------------
__global__ void __launch_bounds__(512)
encode_kernel(const float* __restrict__ x, __nv_bfloat16* __restrict__ out) {
    const int b = blockIdx.x;
    const int f = threadIdx.x >> 2;
    const int j = threadIdx.x & 3;

    const float* xp = x + (size_t)b * (S_SZ * F_INDIM) + f;

    float v[16];
#pragma unroll
    for (int s = 0; s < 16; ++s) {
        float raw = xp[(j * 16 + s) * F_INDIM];
        v[s] = (raw < 0.75f) ? 0.0f : raw;
    }
    float mn = v[0], mx = v[0];
#pragma unroll
    for (int s = 1; s < 16; ++s) { mn = fminf(mn, v[s]); mx = fmaxf(mx, v[s]); }
    mn = fminf(mn, __shfl_xor_sync(0xFFFFFFFFu, mn, 1));
    mn = fminf(mn, __shfl_xor_sync(0xFFFFFFFFu, mn, 2));
    mx = fmaxf(mx, __shfl_xor_sync(0xFFFFFFFFu, mx, 1));
    mx = fmaxf(mx, __shfl_xor_sync(0xFFFFFFFFu, mx, 2));

    float denom = mx - mn + 1e-8f;
    const float TMAX = 11.512935464920229f;

    unsigned pk[8];
#pragma unroll
    for (int i = 0; i < 8; ++i) pk[i] = 0u;
#pragma unroll
    for (int s = 0; s < 16; ++s) {
        float xn = (v[s] - mn) / denom;
        float d  = fmaxf(xn, 0.0100001f);
        float lg = logf(d / (d - 0.01f));
        float tt = (lg * 31.0f) / TMAX;
        float tr = rintf(tt);
        tr = fminf(fmaxf(tr, 0.0f), 31.0f);
        int t = (int)tr;
        pk[t >> 2] += 1u << ((t & 3) * 8);
    }
#pragma unroll
    for (int i = 0; i < 8; ++i) {
        pk[i] += __shfl_xor_sync(0xFFFFFFFFu, pk[i], 1);
        pk[i] += __shfl_xor_sync(0xFFFFFFFFu, pk[i], 2);
    }
#pragma unroll
    for (int i = 0; i < 8; ++i) {
        int t = j * 8 + i;
        unsigned c = (pk[t >> 2] >> ((t & 3) * 8)) & 0xFFu;
        out[((size_t)b * T_STEPS + t) * F_INDIM + f] =
            __float2bfloat16_rn((float)c * (1.0f / 64.0f));
    }
}

// ---------------------------------------------------------------------------
// Fused HMMA GEMM (128x128 tile, K-chunk 64, 3 bf16 splits) + LIF epilogue.
// 8 warps as 4(m) x 2(n); warp tile 32m x 64n via m16n8k16.
// ---------------------------------------------------------------------------
static constexpr int LSMEM = 128 * 132 * 4;   // 67584 >= staging 65536

template <int IN, int H, bool TMAJ>
__global__ void __launch_bounds__(256, 2)
layer_hmma(const __nv_bfloat16* __restrict__ in,
           const __nv_bfloat16* __restrict__ Wsp,
           const float* __restrict__ bias,
           __nv_bfloat16* __restrict__ out_bf,
           float* __restrict__ out_f) {
    extern __shared__ __align__(1024) char smem[];
    const uint32_t sbase = smem_u32(smem);

    const int tid  = threadIdx.x;
    const int wrp  = tid >> 5;
    const int lane = tid & 31;
    const int wm   = wrp & 3;          // m-warp: rows wm*32..+31
    const int wn   = wrp >> 2;         // n-warp: cols wn*64..+63
    const int r0   = blockIdx.x * 128;
    const int N0   = blockIdx.y * 128;

    // ldmatrix per-lane source coordinates
    const int la_row = lane & 15;            // A: row within m16
    const int la_ch  = lane >> 4;            // A: k-chunk half
    const int lb_row = lane & 7;             // B: row within n8
    const int lb_ns  = lane >> 4;            // B: which n8 of the pair
    const int lb_ch  = (lane >> 3) & 1;      // B: k-chunk half

    int mrow[2], nrow[4];
#pragma unroll
    for (int mb = 0; mb < 2; ++mb) mrow[mb] = wm * 32 + mb * 16 + la_row;
#pragma unroll
    for (int p = 0; p < 4; ++p) nrow[p] = wn * 64 + p * 16 + lb_ns * 8 + lb_row;

    float c[2][8][4];
#pragma unroll
    for (int mb = 0; mb < 2; ++mb)
#pragma unroll
        for (int nb = 0; nb < 8; ++nb)
#pragma unroll
            for (int q = 0; q < 4; ++q) c[mb][nb][q] = 0.0f;

    constexpr int NCH = IN / 64;

#pragma unroll 1
    for (int ch = 0; ch < NCH; ++ch) {
        // ---- stage A [128 m][64 k] bf16, swizzled 128B rows ----
        {
            const __nv_bfloat16* Ag = in + (size_t)r0 * IN + ch * 64;
#pragma unroll
            for (int v = tid; v < 1024; v += 256) {
                int m = v >> 3, kv = v & 7;
                uint4 d = *(const uint4*)(Ag + (size_t)m * IN + kv * 8);
                uint32_t off = (uint32_t)(m * 128 + kv * 16);
                off ^= (off >> 3) & 0x70;
                *(uint4*)(smem + off) = d;
            }
        }
        // ---- stage B 3 splits [128 n][64 k] ----
#pragma unroll
        for (int s = 0; s < 3; ++s) {
            const __nv_bfloat16* Bg = Wsp + (size_t)s * H * IN + (size_t)N0 * IN + ch * 64;
#pragma unroll
            for (int v = tid; v < 1024; v += 256) {
                int n = v >> 3, kv = v & 7;
                uint4 d = *(const uint4*)(Bg + (size_t)n * IN + kv * 8);
                uint32_t off = (uint32_t)(n * 128 + kv * 16);
                off ^= (off >> 3) & 0x70;
                *(uint4*)(smem + 16384 + s * 16384 + off) = d;
            }
        }
        __syncthreads();

        // ---- compute: 4 k16 steps x 3 splits ----
#pragma unroll
        for (int ks = 0; ks < 4; ++ks) {
            uint32_t a[2][4];
#pragma unroll
            for (int mb = 0; mb < 2; ++mb) {
                uint32_t off = (uint32_t)(mrow[mb] * 128 +
                               (((ks * 2 + la_ch) * 16) ^ ((mrow[mb] & 7) << 4)));
                ldsm4(a[mb][0], a[mb][1], a[mb][2], a[mb][3], sbase + off);
            }
#pragma unroll
            for (int s = 0; s < 3; ++s) {
                const uint32_t bofs = sbase + 16384 + s * 16384;
#pragma unroll
                for (int p = 0; p < 4; ++p) {
                    uint32_t b0, b1, b2, b3;
                    uint32_t off = (uint32_t)(nrow[p] * 128 +
                                   (((ks * 2 + lb_ch) * 16) ^ ((nrow[p] & 7) << 4)));
                    ldsm4(b0, b1, b2, b3, bofs + off);
                    mma16816(c[0][2 * p + 0], a[0], b0, b1);
                    mma16816(c[1][2 * p + 0], a[1], b0, b1);
                    mma16816(c[0][2 * p + 1], a[0], b2, b3);
                    mma16816(c[1][2 * p + 1], a[1], b2, b3);
                }
            }
        }
        __syncthreads();
    }

    // ---- epilogue: C frags -> smem [128 m][132 stride] f32 ----
    float* scur = (float*)smem;
#pragma unroll
    for (int mb = 0; mb < 2; ++mb)
#pragma unroll
        for (int nb = 0; nb < 8; ++nb) {
            int row = wm * 32 + mb * 16 + (lane >> 2);
            int col = wn * 64 + nb * 8 + 2 * (lane & 3);
            *(float2*)&scur[(size_t)row * 132 + col] =
                make_float2(c[mb][nb][0], c[mb][nb][1]);
            *(float2*)&scur[(size_t)(row + 8) * 132 + col] =
                make_float2(c[mb][nb][2], c[mb][nb][3]);
        }
    __syncthreads();

    // ---- fused LIF scan: 512 (bl, h) tasks over 256 threads ----
#pragma unroll
    for (int task = tid; task < 512; task += 256) {
        const int bl = task >> 7;          // batch within tile (4 per tile)
        const int h  = task & 127;
        const float bv = bias[N0 + h];
        float mem = 0.0f;
#pragma unroll
        for (int t = 0; t < T_STEPS; ++t) {
            float a2  = scur[(size_t)(bl * 32 + t) * 132 + h];
            float cur = __fadd_rn(a2, bv);
            float r   = (mem > 1.0f) ? 1.0f : 0.0f;
            mem = __fsub_rn(__fadd_rn(__fmul_rn(0.9f, mem), cur), r);
            float spk = (mem > 1.0f) ? 1.0f : 0.0f;
            if (TMAJ) {
                out_f[((size_t)t * B_SZ + blockIdx.x * 4 + bl) * H + N0 + h] = spk;
            } else {
                out_bf[(size_t)(r0 + bl * 32 + t) * H + N0 + h] = __float2bfloat16_rn(spk);
            }
        }
    }
}

// ---------------------------------------------------------------------------
extern "C" void kernel_launch(void* const* d_in, const int* in_sizes, int n_in,
                              void* d_out, int out_size) {
    const float* x  = (const float*)d_in[0];
    const float* W1 = (const float*)d_in[1];
    const float* b1 = (const float*)d_in[2];
    const float* W2 = (const float*)d_in[3];
    const float* b2 = (const float*)d_in[4];
    const float* W3 = (const float*)d_in[5];
    const float* b3 = (const float*)d_in[6];
    float* out = (float*)d_out;

    __nv_bfloat16 *spk0, *spk1, *spk2, *w1s, *w2s, *w3s;
    cudaGetSymbolAddress((void**)&spk0, g_spk0);
    cudaGetSymbolAddress((void**)&spk1, g_spk1);
    cudaGetSymbolAddress((void**)&spk2, g_spk2);
    cudaGetSymbolAddress((void**)&w1s, g_W1s);
    cudaGetSymbolAddress((void**)&w2s, g_W2s);
    cudaGetSymbolAddress((void**)&w3s, g_W3s);

    cudaFuncSetAttribute(layer_hmma<F_INDIM, H1, false>,
                         cudaFuncAttributeMaxDynamicSharedMemorySize, LSMEM);
    cudaFuncSetAttribute(layer_hmma<H1, H2, false>,
                         cudaFuncAttributeMaxDynamicSharedMemorySize, LSMEM);
    cudaFuncSetAttribute(layer_hmma<H2, H3, true>,
                         cudaFuncAttributeMaxDynamicSharedMemorySize, LSMEM);

    split_kernel<<<(H1 * F_INDIM + 255) / 256, 256>>>(W1, w1s, H1 * F_INDIM);
    split_kernel<<<(H2 * H1 + 255) / 256, 256>>>(W2, w2s, H2 * H1);
    split_kernel<<<(H3 * H2 + 255) / 256, 256>>>(W3, w3s, H3 * H2);

    encode_kernel<<<B_SZ, 512>>>(x, spk0);

    layer_hmma<F_INDIM, H1, false>
        <<<dim3(M_ROWS / 128, H1 / 128), 256, LSMEM>>>(spk0, w1s, b1, spk1, nullptr);
    layer_hmma<H1, H2, false>
        <<<dim3(M_ROWS / 128, H2 / 128), 256, LSMEM>>>(spk1, w2s, b2, spk2, nullptr);
    layer_hmma<H2, H3, true>
        <<<dim3(M_ROWS / 128, H3 / 128), 256, LSMEM>>>(spk2, w3s, b3, nullptr, out);
}

// round 6
// speedup vs baseline: 3.5363x; 1.2851x over previous
#include <cuda_runtime.h>
#include <cuda_bf16.h>
#include <cstdint>

#define T_STEPS 32
#define B_SZ    512
#define S_SZ    64
#define F_INDIM 128
#define H1      256
#define H2      256
#define H3      128
#define M_ROWS  (T_STEPS * B_SZ)   // 16384

// Scratch (no cudaMalloc): device globals. Spike buffers b-major: row = b*32+t.
__device__ __nv_bfloat16 g_spk0[M_ROWS * F_INDIM];
__device__ __nv_bfloat16 g_spk1[M_ROWS * H1];
__device__ __nv_bfloat16 g_spk2[M_ROWS * H2];
__device__ __nv_bfloat16 g_W1s[3 * H1 * F_INDIM];   // [split][h][i] (k-contiguous)
__device__ __nv_bfloat16 g_W2s[3 * H2 * H1];
__device__ __nv_bfloat16 g_W3s[3 * H3 * H2];

__device__ __forceinline__ uint32_t smem_u32(const void* p) {
    uint32_t a;
    asm("{ .reg .u64 t; cvta.to.shared.u64 t, %1; cvt.u32.u64 %0, t; }" : "=r"(a) : "l"(p));
    return a;
}
__device__ __forceinline__ void ldsm4(uint32_t& r0, uint32_t& r1, uint32_t& r2,
                                      uint32_t& r3, uint32_t addr) {
    asm volatile("ldmatrix.sync.aligned.m8n8.x4.shared.b16 {%0,%1,%2,%3}, [%4];"
                 : "=r"(r0), "=r"(r1), "=r"(r2), "=r"(r3) : "r"(addr));
}
__device__ __forceinline__ void mma16816(float* c, const uint32_t* a,
                                         uint32_t b0, uint32_t b1) {
    asm volatile(
        "mma.sync.aligned.m16n8k16.row.col.f32.bf16.bf16.f32 "
        "{%0,%1,%2,%3}, {%4,%5,%6,%7}, {%8,%9}, {%0,%1,%2,%3};"
        : "+f"(c[0]), "+f"(c[1]), "+f"(c[2]), "+f"(c[3])
        : "r"(a[0]), "r"(a[1]), "r"(a[2]), "r"(a[3]), "r"(b0), "r"(b1));
}
__device__ __forceinline__ void cp16(uint32_t dst, const void* src) {
    asm volatile("cp.async.cg.shared.global [%0], [%1], 16;" :: "r"(dst), "l"(src));
}
#define CP_COMMIT() asm volatile("cp.async.commit_group;" ::: "memory")
#define CP_WAIT(n)  asm volatile("cp.async.wait_group %0;" :: "n"(n) : "memory")

// ---------------------------------------------------------------------------
// Combined weight split (all 3 matrices, one launch). Exact bf16 RN splits.
// ---------------------------------------------------------------------------
__global__ void split3_kernel(const float* __restrict__ W1, const float* __restrict__ W2,
                              const float* __restrict__ W3,
                              __nv_bfloat16* __restrict__ o1, __nv_bfloat16* __restrict__ o2,
                              __nv_bfloat16* __restrict__ o3) {
    const int n1 = H1 * F_INDIM, n2 = H2 * H1, n3 = H3 * H2;
    int idx = blockIdx.x * blockDim.x + threadIdx.x;
    const float* W; __nv_bfloat16* o; int n, i;
    if (idx < n1)              { W = W1; o = o1; n = n1; i = idx; }
    else if (idx < n1 + n2)    { W = W2; o = o2; n = n2; i = idx - n1; }
    else if (idx < n1 + n2 + n3) { W = W3; o = o3; n = n3; i = idx - n1 - n2; }
    else return;
    float w = W[i];
    __nv_bfloat16 h1 = __float2bfloat16_rn(w);
    float r1 = w - __bfloat162float(h1);
    __nv_bfloat16 h2 = __float2bfloat16_rn(r1);
    float r2 = r1 - __bfloat162float(h2);
    o[i] = h1; o[n + i] = h2; o[2 * n + i] = __float2bfloat16_rn(r2);
}

// ---------------------------------------------------------------------------
// Latency encoder with zero-shortcut. All gated-to-zero values in a thread
// share identical xn = (0 - mn)/denom -> one logf classifies them all
// (bit-identical to per-value evaluation). Nonzeros loop via ffs-compaction.
// ---------------------------------------------------------------------------
__global__ void __launch_bounds__(512)
encode_kernel(const float* __restrict__ x, __nv_bfloat16* __restrict__ out) {
    const int b = blockIdx.x;
    const int f = threadIdx.x >> 2;
    const int j = threadIdx.x & 3;

    const float* xp = x + (size_t)b * (S_SZ * F_INDIM) + f;

    float mn = 1e30f, mx = -1e30f;
    unsigned mask = 0;
#pragma unroll
    for (int s = 0; s < 16; ++s) {
        float raw = xp[(j * 16 + s) * F_INDIM];
        float g = (raw < 0.75f) ? 0.0f : raw;
        mn = fminf(mn, g);
        mx = fmaxf(mx, g);
        mask |= (g != 0.0f) ? (1u << s) : 0u;
    }
    mn = fminf(mn, __shfl_xor_sync(0xFFFFFFFFu, mn, 1));
    mn = fminf(mn, __shfl_xor_sync(0xFFFFFFFFu, mn, 2));
    mx = fmaxf(mx, __shfl_xor_sync(0xFFFFFFFFu, mx, 1));
    mx = fmaxf(mx, __shfl_xor_sync(0xFFFFFFFFu, mx, 2));

    float denom = mx - mn + 1e-8f;
    const float TMAX = 11.512935464920229f;

    unsigned pk[8];
#pragma unroll
    for (int i = 0; i < 8; ++i) pk[i] = 0u;

    // zero bucket: one evaluation covers all (16 - nz) zeros
    int zc = 16 - __popc(mask);
    if (zc) {
        float xn = (0.0f - mn) / denom;
        float d  = fmaxf(xn, 0.0100001f);
        float lg = logf(d / (d - 0.01f));
        float tt = (lg * 31.0f) / TMAX;
        float tr = rintf(tt);
        tr = fminf(fmaxf(tr, 0.0f), 31.0f);
        int t = (int)tr;
        pk[t >> 2] += (unsigned)zc << ((t & 3) * 8);
    }
    // nonzero values
    while (mask) {
        int s = __ffs(mask) - 1;
        mask &= mask - 1;
        float v  = xp[(j * 16 + s) * F_INDIM];   // L1 hit; raw >= 0.75 == gated value
        float xn = (v - mn) / denom;
        float d  = fmaxf(xn, 0.0100001f);
        float lg = logf(d / (d - 0.01f));
        float tt = (lg * 31.0f) / TMAX;
        float tr = rintf(tt);
        tr = fminf(fmaxf(tr, 0.0f), 31.0f);
        int t = (int)tr;
        pk[t >> 2] += 1u << ((t & 3) * 8);
    }

#pragma unroll
    for (int i = 0; i < 8; ++i) {
        pk[i] += __shfl_xor_sync(0xFFFFFFFFu, pk[i], 1);
        pk[i] += __shfl_xor_sync(0xFFFFFFFFu, pk[i], 2);
    }
#pragma unroll
    for (int i = 0; i < 8; ++i) {
        int t = j * 8 + i;
        unsigned c = (pk[t >> 2] >> ((t & 3) * 8)) & 0xFFu;
        out[((size_t)b * T_STEPS + t) * F_INDIM + f] =
            __float2bfloat16_rn((float)c * (1.0f / 64.0f));
    }
}

// ---------------------------------------------------------------------------
// Fused HMMA GEMM + LIF. Tile TM x 128, 512 threads (16 warps: 4m x 4n),
// warp tile (TM/4)m x 32n. cp.async 2-stage pipeline over K-chunks of 64.
// ---------------------------------------------------------------------------
template <int IN, int H, int TM, bool TMAJ>
__global__ void __launch_bounds__(512, 1)
layer_hmma(const __nv_bfloat16* __restrict__ in,
           const __nv_bfloat16* __restrict__ Wsp,
           const float* __restrict__ bias,
           __nv_bfloat16* __restrict__ out_bf,
           float* __restrict__ out_f) {
    constexpr int A_BYTES = TM * 128;            // TM rows x 64k bf16
    constexpr int SS      = A_BYTES + 3 * 16384; // stage: A + 3 B splits
    constexpr int MB      = TM / 64;             // m16 frags per warp
    constexpr int NCH     = IN / 64;

    extern __shared__ __align__(1024) char smem[];
    const uint32_t sbase = smem_u32(smem);

    const int tid  = threadIdx.x;
    const int wrp  = tid >> 5;
    const int lane = tid & 31;
    const int wm   = wrp & 3;
    const int wn   = wrp >> 2;
    const int r0   = blockIdx.x * TM;
    const int N0   = blockIdx.y * 128;

    const int la_row = lane & 15;
    const int la_ch  = lane >> 4;
    const int lb_row = lane & 7;
    const int lb_ns  = lane >> 4;
    const int lb_ch  = (lane >> 3) & 1;

    int mrow[MB], nrow[2];
#pragma unroll
    for (int mb = 0; mb < MB; ++mb) mrow[mb] = wm * (TM / 4) + mb * 16 + la_row;
#pragma unroll
    for (int p = 0; p < 2; ++p) nrow[p] = wn * 32 + p * 16 + lb_ns * 8 + lb_row;

    const __nv_bfloat16* Ag = in + (size_t)r0 * IN;

    // stage issuer: A [TM][64] + B 3x[128][64], swizzled 128B rows
    auto issue_stage = [&](int ch, int buf) {
        const uint32_t dstA = sbase + buf * SS;
#pragma unroll
        for (int it = 0; it < TM / 64; ++it) {
            int v = tid + it * 512, m = v >> 3, kv = v & 7;
            uint32_t off = (uint32_t)(m * 128 + kv * 16);
            off ^= (off >> 3) & 0x70;
            cp16(dstA + off, Ag + (size_t)m * IN + ch * 64 + kv * 8);
        }
        const uint32_t dstB = dstA + A_BYTES;
#pragma unroll
        for (int it = 0; it < 6; ++it) {
            int v = tid + it * 512, s = v >> 10, w = v & 1023, n = w >> 3, kv = w & 7;
            uint32_t off = (uint32_t)(n * 128 + kv * 16);
            off ^= (off >> 3) & 0x70;
            cp16(dstB + s * 16384 + off,
                 Wsp + (size_t)s * H * IN + (size_t)(N0 + n) * IN + ch * 64 + kv * 8);
        }
        CP_COMMIT();
    };

    float c[MB][4][4];
#pragma unroll
    for (int mb = 0; mb < MB; ++mb)
#pragma unroll
        for (int nb = 0; nb < 4; ++nb)
#pragma unroll
            for (int q = 0; q < 4; ++q) c[mb][nb][q] = 0.0f;

    issue_stage(0, 0);

#pragma unroll 1
    for (int ch = 0; ch < NCH; ++ch) {
        if (ch + 1 < NCH) {
            issue_stage(ch + 1, (ch + 1) & 1);
            CP_WAIT(1);
        } else {
            CP_WAIT(0);
        }
        __syncthreads();

        const uint32_t bufA = sbase + (ch & 1) * SS;
        const uint32_t bufB = bufA + A_BYTES;
#pragma unroll
        for (int ks = 0; ks < 4; ++ks) {
            uint32_t a[MB][4];
#pragma unroll
            for (int mb = 0; mb < MB; ++mb) {
                uint32_t off = (uint32_t)(mrow[mb] * 128 +
                               (((ks * 2 + la_ch) * 16) ^ ((mrow[mb] & 7) << 4)));
                ldsm4(a[mb][0], a[mb][1], a[mb][2], a[mb][3], bufA + off);
            }
#pragma unroll
            for (int s = 0; s < 3; ++s) {
#pragma unroll
                for (int p = 0; p < 2; ++p) {
                    uint32_t b0, b1, b2, b3;
                    uint32_t off = (uint32_t)(nrow[p] * 128 +
                                   (((ks * 2 + lb_ch) * 16) ^ ((nrow[p] & 7) << 4)));
                    ldsm4(b0, b1, b2, b3, bufB + s * 16384 + off);
#pragma unroll
                    for (int mb = 0; mb < MB; ++mb) {
                        mma16816(c[mb][2 * p + 0], a[mb], b0, b1);
                        mma16816(c[mb][2 * p + 1], a[mb], b2, b3);
                    }
                }
            }
        }
        __syncthreads();
    }

    // ---- epilogue: C frags -> smem [TM m][132 stride] f32 ----
    float* scur = (float*)smem;
#pragma unroll
    for (int mb = 0; mb < MB; ++mb)
#pragma unroll
        for (int nb = 0; nb < 4; ++nb) {
            int row = wm * (TM / 4) + mb * 16 + (lane >> 2);
            int col = wn * 32 + nb * 8 + 2 * (lane & 3);
            *(float2*)&scur[(size_t)row * 132 + col] =
                make_float2(c[mb][nb][0], c[mb][nb][1]);
            *(float2*)&scur[(size_t)(row + 8) * 132 + col] =
                make_float2(c[mb][nb][2], c[mb][nb][3]);
        }
    __syncthreads();

    // ---- fused LIF scan: (TM/32)*128 tasks over 512 threads ----
#pragma unroll
    for (int task = tid; task < (TM / 32) * 128; task += 512) {
        const int bl = task >> 7;
        const int h  = task & 127;
        const float bv = bias[N0 + h];
        const int bglob = blockIdx.x * (TM / 32) + bl;
        float mem = 0.0f;
#pragma unroll
        for (int t = 0; t < T_STEPS; ++t) {
            float a2  = scur[(size_t)(bl * 32 + t) * 132 + h];
            float cur = __fadd_rn(a2, bv);
            float r   = (mem > 1.0f) ? 1.0f : 0.0f;
            mem = __fsub_rn(__fadd_rn(__fmul_rn(0.9f, mem), cur), r);
            float spk = (mem > 1.0f) ? 1.0f : 0.0f;
            if (TMAJ) {
                out_f[((size_t)t * B_SZ + bglob) * H + N0 + h] = spk;
            } else {
                out_bf[(size_t)(r0 + bl * 32 + t) * H + N0 + h] = __float2bfloat16_rn(spk);
            }
        }
    }
}

// ---------------------------------------------------------------------------
extern "C" void kernel_launch(void* const* d_in, const int* in_sizes, int n_in,
                              void* d_out, int out_size) {
    const float* x  = (const float*)d_in[0];
    const float* W1 = (const float*)d_in[1];
    const float* b1 = (const float*)d_in[2];
    const float* W2 = (const float*)d_in[3];
    const float* b2 = (const float*)d_in[4];
    const float* W3 = (const float*)d_in[5];
    const float* b3 = (const float*)d_in[6];
    float* out = (float*)d_out;

    __nv_bfloat16 *spk0, *spk1, *spk2, *w1s, *w2s, *w3s;
    cudaGetSymbolAddress((void**)&spk0, g_spk0);
    cudaGetSymbolAddress((void**)&spk1, g_spk1);
    cudaGetSymbolAddress((void**)&spk2, g_spk2);
    cudaGetSymbolAddress((void**)&w1s, g_W1s);
    cudaGetSymbolAddress((void**)&w2s, g_W2s);
    cudaGetSymbolAddress((void**)&w3s, g_W3s);

    constexpr int SM256 = 2 * (256 * 128 + 3 * 16384);   // 163840
    constexpr int SM128 = 2 * (128 * 128 + 3 * 16384);   // 131072
    cudaFuncSetAttribute(layer_hmma<F_INDIM, H1, 256, false>,
                         cudaFuncAttributeMaxDynamicSharedMemorySize, SM256);
    cudaFuncSetAttribute(layer_hmma<H1, H2, 256, false>,
                         cudaFuncAttributeMaxDynamicSharedMemorySize, SM256);
    cudaFuncSetAttribute(layer_hmma<H2, H3, 128, true>,
                         cudaFuncAttributeMaxDynamicSharedMemorySize, SM128);

    int ntot = H1 * F_INDIM + H2 * H1 + H3 * H2;
    split3_kernel<<<(ntot + 255) / 256, 256>>>(W1, W2, W3, w1s, w2s, w3s);

    encode_kernel<<<B_SZ, 512>>>(x, spk0);

    layer_hmma<F_INDIM, H1, 256, false>
        <<<dim3(M_ROWS / 256, H1 / 128), 512, SM256>>>(spk0, w1s, b1, spk1, nullptr);
    layer_hmma<H1, H2, 256, false>
        <<<dim3(M_ROWS / 256, H2 / 128), 512, SM256>>>(spk1, w2s, b2, spk2, nullptr);
    layer_hmma<H2, H3, 128, true>
        <<<dim3(M_ROWS / 128, H3 / 128), 512, SM128>>>(spk2, w3s, b3, nullptr, out);
}